// round 13
// baseline (speedup 1.0000x reference)
#include <cuda_runtime.h>
#include <math.h>

#define NB   64
#define NSZ  512
#define NN   (NSZ*NSZ)
#define PI_D 3.14159265358979323846
#define PIF32 3.14159274101257324219f
#define PIH32 1.57079637050628662109f

__device__ float2 g_cA[NB*NN];
__device__ float2 g_cB[NB*NN];
__device__ float  g_r [NB*NN];
__device__ float2 g_sA[NN];
__device__ float2 g_sB[NN];
__device__ float2 g_Flp0[NN];
__device__ float2 g_Fref[NN];
__device__ float  g_d0[NN];
// 0 bg_img[64] | 64 bg_apo[64] | 128 bg_apo_ref | 129 bg_lp0 | 130 bg_lp[64] |
// 258 scale[64] | 322 angle[64] | 386 tvec[128](..513) | 514 sinA[64](..577) | 578 cosA[64](..641)
__device__ float    g_sc[700];
__device__ unsigned g_mxu[64];
__device__ float2   g_part[64*8];
__device__ float2 g_tw[512];
__device__ float  g_rad[512], g_ths[512], g_thc[512], g_lin[512];
__device__ double g_apd[512];
__device__ float  g_lb;

__device__ __forceinline__ unsigned fkey(float x){
    unsigned u = __float_as_uint(x);
    return (u & 0x80000000u) ? ~u : (u | 0x80000000u);
}
__device__ __forceinline__ float finv(unsigned k){
    unsigned u = (k & 0x80000000u) ? (k & 0x7FFFFFFFu) : ~k;
    return __uint_as_float(u);
}
// correctly-rounded f32 complex magnitude (glibc hypotf equivalent)
__device__ __forceinline__ float mag32(float x, float y){
    return (float)sqrt((double)x*(double)x + (double)y*(double)y);
}
__device__ __forceinline__ int border_idx(int i, int r){
    if (i < r*NSZ) return i;
    i -= r*NSZ;
    if (i < r*NSZ){ int y = NSZ - r + i/NSZ; return y*NSZ + (i%NSZ); }
    i -= r*NSZ;
    int row = i/(2*r), c = i%(2*r);
    return (r+row)*NSZ + ((c < r) ? c : (NSZ - 2*r + c));
}
// reference fp32 bilinear, exact op order, no contraction
__device__ __forceinline__ float bilin(const float* __restrict__ img, float ry, float rx, float bg){
    float y0f = floorf(ry), x0f = floorf(rx);
    float wy = __fsub_rn(ry, y0f), wx = __fsub_rn(rx, x0f);
    int y0 = (int)y0f, x0 = (int)x0f;
    float v[4];
#pragma unroll
    for (int k = 0; k < 4; ++k){
        int yi = y0 + (k>>1), xi = x0 + (k&1);
        bool ok = (yi>=0)&&(yi<NSZ)&&(xi>=0)&&(xi<NSZ);
        int yc = min(max(yi,0),NSZ-1), xc = min(max(xi,0),NSZ-1);
        v[k] = ok ? img[yc*NSZ+xc] : bg;
    }
    float oy = __fsub_rn(1.f, wy), ox = __fsub_rn(1.f, wx);
    float t0 = __fmul_rn(__fmul_rn(v[0], oy), ox);
    float t1 = __fmul_rn(__fmul_rn(v[1], oy), wx);
    float t2 = __fmul_rn(__fmul_rn(v[2], wy), ox);
    float t3 = __fmul_rn(__fmul_rn(v[3], wy), wx);
    return __fadd_rn(__fadd_rn(__fadd_rn(t0, t1), t2), t3);
}
__device__ __forceinline__ float2 cadd(float2 a, float2 b){ return make_float2(a.x+b.x, a.y+b.y); }
__device__ __forceinline__ float2 csub(float2 a, float2 b){ return make_float2(a.x-b.x, a.y-b.y); }
__device__ __forceinline__ float2 cmul(float2 a, float2 b){
    return make_float2(fmaf(a.x,b.x,-a.y*b.y), fmaf(a.x,b.y, a.y*b.x));
}
__device__ __forceinline__ float2 cmuli(float2 a, float s){ return make_float2(-s*a.y, s*a.x); }
__device__ __forceinline__ void fft8(float2* v, float s){
    float2 b0=cadd(v[0],v[4]), b1=csub(v[0],v[4]);
    float2 b2=cadd(v[2],v[6]), b3=csub(v[2],v[6]);
    float2 b4=cadd(v[1],v[5]), b5=csub(v[1],v[5]);
    float2 b6=cadd(v[3],v[7]), b7=csub(v[3],v[7]);
    float2 t3=cmuli(b3,s), t7=cmuli(b7,s);
    float2 c0=cadd(b0,b2), c2=csub(b0,b2), c1=cadd(b1,t3), c3=csub(b1,t3);
    float2 c4=cadd(b4,b6), c6=csub(b4,b6), c5=cadd(b5,t7), c7=csub(b5,t7);
    const float r2 = 0.70710678118654752440f;
    float2 w1 = make_float2( r2, s*r2), w3 = make_float2(-r2, s*r2);
    float2 d5=cmul(c5,w1), d6=cmuli(c6,s), d7=cmul(c7,w3);
    v[0]=cadd(c0,c4); v[4]=csub(c0,c4);
    v[1]=cadd(c1,d5); v[5]=csub(c1,d5);
    v[2]=cadd(c2,d6); v[6]=csub(c2,d6);
    v[3]=cadd(c3,d7); v[7]=csub(c3,d7);
}
#define SPAD(i) ((i) + ((i)>>3))

struct FftArgs {
    const float2* srcC; const float* srcF;
    float2* dstC; float* dstF;
    const float* bg; const float2* F0; const float* img;
};

// PRE: 0 loadC,1 packF,2 apodize,3 lp-gather,4 crosspow,5 transform
// POST: 0 storeC,1 specmag,2 absshift,3 storeC+max        DIR: 0 fwd, 1 inv
template<int PRE, int POST, int DIR>
__global__ void __launch_bounds__(256) ia_fft(FftArgs A){
    __shared__ float2 sm[4][576];
    __shared__ float2 tws[512];
    __shared__ float  red[256];
    const int tid = threadIdx.x;
    tws[tid] = g_tw[tid]; tws[tid+256] = g_tw[tid+256];
    const int rl = tid >> 6, j = tid & 63;
    const int gr = blockIdx.x*4 + rl;
    const int b = gr >> 9, rr = gr & 511;
    const float sgn = DIR ? 1.f : -1.f;
    float2 v[8];

    if (PRE == 0){
        const float2* s = A.srcC + (size_t)gr*NSZ;
#pragma unroll
        for (int r = 0; r < 8; ++r) v[r] = s[j + 64*r];
    } else if (PRE == 1){
        const float* s = A.srcF + (size_t)gr*NSZ;
#pragma unroll
        for (int r = 0; r < 8; ++r) v[r] = make_float2(s[j+64*r], 0.f);
    } else if (PRE == 2){
        const double ay = g_apd[rr];
        const float bgv = A.bg[b];
        const float* s = A.srcF + (size_t)gr*NSZ;
#pragma unroll
        for (int r = 0; r < 8; ++r){
            int p = j + 64*r;
            float a = (float)(ay * g_apd[p]);   // numpy fp64 outer, rounded once
            float t = __fmul_rn(s[p], a);
            float u = __fmul_rn(bgv, __fsub_rn(1.f, a));
            v[r] = make_float2(__fadd_rn(t, u), 0.f);
        }
    } else if (PRE == 3){
        const float sn = g_ths[rr], cs = g_thc[rr], bgv = A.bg[b];
        const float* dd = A.srcF + (size_t)b*NN;
#pragma unroll
        for (int r = 0; r < 8; ++r){
            int p = j + 64*r;
            float rad = g_rad[p];
            float y = __fadd_rn(__fmul_rn(rad, sn), 256.f);
            float x = __fadd_rn(__fmul_rn(rad, cs), 256.f);
            v[r] = make_float2(bilin(dd, x, y, bgv), 0.f);  // src transposed -> swap
        }
    } else if (PRE == 4){
        const float2* s  = A.srcC + (size_t)gr*NSZ;
        const float2* f0 = A.F0   + (size_t)rr*NSZ;
        const float eps  = __fmul_rn(__uint_as_float(g_mxu[b]), 1e-15f);
#pragma unroll
        for (int r = 0; r < 8; ++r){
            int p = j + 64*r;
            float2 c = s[p], a = f0[p];
            float den = __fadd_rn(__fmul_rn(mag32(a.x,a.y), mag32(c.x,c.y)), eps);
            float re = __fadd_rn(__fmul_rn(a.x,c.x), __fmul_rn(a.y,c.y));
            float im = __fsub_rn(__fmul_rn(a.y,c.x), __fmul_rn(a.x,c.y));
            v[r] = make_float2(__fdiv_rn(re,den), __fdiv_rn(im,den));
        }
    } else {
        float scl = g_sc[258+b];
        float ca = g_sc[578+b], sa = g_sc[514+b];
        const float bgv = g_sc[b];
        const float* im = A.img + (size_t)b*NN;
        float dy = __fsub_rn((float)rr, 255.5f);   // tvec = 0 here
#pragma unroll
        for (int r = 0; r < 8; ++r){
            float dx = __fsub_rn((float)(j + 64*r), 255.5f);
            float sy = __fadd_rn(__fdiv_rn(__fsub_rn(__fmul_rn(ca,dy), __fmul_rn(sa,dx)), scl), 255.5f);
            float sx = __fadd_rn(__fdiv_rn(__fadd_rn(__fmul_rn(sa,dy), __fmul_rn(ca,dx)), scl), 255.5f);
            v[r] = make_float2(bilin(im, sy, sx, bgv), 0.f);
        }
    }

    fft8(v, sgn);
#pragma unroll
    for (int r = 0; r < 8; ++r) sm[rl][SPAD(8*j + r)] = v[r];
    __syncthreads();
#pragma unroll
    for (int r = 0; r < 8; ++r) v[r] = sm[rl][SPAD(j + 64*r)];
    __syncthreads();
    {
        const int kb = (j & 7) * 8;
#pragma unroll
        for (int r = 1; r < 8; ++r){
            float2 w = tws[(kb*r) & 511];
            if (DIR) w.y = -w.y;
            v[r] = cmul(v[r], w);
        }
        fft8(v, sgn);
        const int base = (j >> 3)*64 + (j & 7);
#pragma unroll
        for (int r = 0; r < 8; ++r) sm[rl][SPAD(base + 8*r)] = v[r];
    }
    __syncthreads();
#pragma unroll
    for (int r = 0; r < 8; ++r) v[r] = sm[rl][SPAD(j + 64*r)];
#pragma unroll
    for (int r = 1; r < 8; ++r){
        float2 w = tws[(j*r) & 511];
        if (DIR) w.y = -w.y;
        v[r] = cmul(v[r], w);
    }
    fft8(v, sgn);

    if (POST == 0){
        float2* d = A.dstC + (size_t)gr*NSZ;
        const float s5 = DIR ? (1.f/512.f) : 1.f;   // exact pow2
#pragma unroll
        for (int r = 0; r < 8; ++r) d[j+64*r] = make_float2(v[r].x*s5, v[r].y*s5);
    } else if (POST == 1){
        const int y = (rr + 256) & 511;
        float* d = A.dstF + (size_t)b*NN + (size_t)y*NSZ;
        const float yyv = g_lin[y];
#pragma unroll
        for (int r = 0; r < 8; ++r){
            int x = (j + 64*r + 256) & 511;
            float xxv = g_lin[x];
            float rad = __fsqrt_rn(__fadd_rn(__fmul_rn(yyv,yyv), __fmul_rn(xxv,xxv)));
            float c = (float)cos((double)rad);      // correctly-rounded cosf
            float f = (rad > PIH32) ? 1.0f : __fsub_rn(1.0f, __fmul_rn(c,c));
            d[x] = __fmul_rn(mag32(v[r].x, v[r].y), f);
        }
    } else if (POST == 2){
        const int y = (rr + 256) & 511;
        float* d = A.dstF + (size_t)b*NN + (size_t)y*NSZ;
#pragma unroll
        for (int r = 0; r < 8; ++r){
            int x = (j + 64*r + 256) & 511;
            float xr = __fmul_rn(v[r].x, 1.f/512.f);
            float xi = __fmul_rn(v[r].y, 1.f/512.f);
            d[x] = mag32(xr, xi);
        }
    } else {
        float2* d = A.dstC + (size_t)gr*NSZ;
        float m = 0.f;
#pragma unroll
        for (int r = 0; r < 8; ++r){
            d[j+64*r] = v[r];
            m = fmaxf(m, mag32(v[r].x, v[r].y));
        }
        red[tid] = m; __syncthreads();
        for (int s2 = 128; s2 > 0; s2 >>= 1){
            if (tid < s2) red[tid] = fmaxf(red[tid], red[tid+s2]);
            __syncthreads();
        }
        if (tid == 0) atomicMax(&g_mxu[b], __float_as_uint(red[0]));
    }
}

// 256 threads + stride loop: launch-safe at ANY register count
__global__ void __launch_bounds__(256) ia_setup(){
    // glibc chain: lgf = fl32(log(281.6f)); arg = lgf/512 (exact); lb = fl32(exp(arg))
    const float lgf = (float)log(281.600006103515625);
    const float arg = lgf / 512.0f;
    const float lb  = (float)exp((double)arg);
    const double loglb = log((double)lb);
    for (int i = threadIdx.x; i < 512; i += 256){
        double a = -2.0*PI_D*(double)i/512.0;
        g_tw[i] = make_float2((float)cos(a), (float)sin(a));
        g_rad[i] = (float)exp((double)i * loglb);      // == glibc powf(lb, i)
        float af = __fmul_rn((float)i, PIF32/512.0f);  // exact step pi/512
        g_ths[i] = (float)sin(-(double)af);
        g_thc[i] = (float)cos(-(double)af);
        const float dl = PIF32/511.0f;
        g_lin[i] = __fadd_rn(__fmul_rn((float)i, dl), -PIH32);
        double t0 = 1.0;
        if (i < 61)        t0 = 0.5*(1.0 - cos(2.0*PI_D*(double)i/121.0));
        else if (i >= 451){ int jj = i - 390; t0 = 0.5*(1.0 - cos(2.0*PI_D*(double)jj/121.0)); }
        g_apd[i] = t0;
    }
    if (threadIdx.x == 0) g_lb = lb;
    if (threadIdx.x < 64) g_mxu[threadIdx.x] = 0u;
}
__global__ void ia_clear(){ g_mxu[threadIdx.x] = 0u; }

__global__ void __launch_bounds__(256) ia_border_median(const float* __restrict__ base, int radius, float* __restrict__ out){
    __shared__ unsigned hist[256];
    __shared__ unsigned s_prefix, s_rank;
    __shared__ float    s_val[2];
    const float* img = base + (size_t)blockIdx.x * NN;
    const int r = radius;
    const int n = 2*r*NSZ + 2*r*(NSZ-2*r);
    const int t = threadIdx.x;
    for (int which = 0; which < 2; ++which){
        int k = n/2 - 1 + which;
        if (t==0){ s_prefix = 0u; s_rank = (unsigned)k; }
        __syncthreads();
        for (int shift = 24; shift >= 0; shift -= 8){
            hist[t] = 0u; __syncthreads();
            unsigned pmask = (shift==24) ? 0u : (0xFFFFFFFFu << (shift+8));
            unsigned pref = s_prefix, rank = s_rank;
            for (int i = t; i < n; i += 256){
                unsigned key = fkey(img[border_idx(i, r)]);
                if ((key & pmask) == pref) atomicAdd(&hist[(key>>shift)&255u], 1u);
            }
            __syncthreads();
            if (t==0){
                unsigned cum = 0;
                for (int jj = 0; jj < 256; ++jj){
                    unsigned h = hist[jj];
                    if (cum + h > rank){ s_prefix = pref | ((unsigned)jj << shift);
                                         s_rank = rank - cum; break; }
                    cum += h;
                }
            }
            __syncthreads();
        }
        if (t==0) s_val[which] = finv(s_prefix);
        __syncthreads();
    }
    if (t==0) out[blockIdx.x] = __fmul_rn(0.5f, __fadd_rn(s_val[0], s_val[1]));
}

__global__ void ia_transpose(const float2* __restrict__ in, float2* __restrict__ out){
    __shared__ float2 tile[32][33];
    const size_t boff = (size_t)blockIdx.z * NN;
    int x = blockIdx.x*32 + threadIdx.x, y0 = blockIdx.y*32 + threadIdx.y;
#pragma unroll
    for (int i = 0; i < 32; i += 8)
        tile[threadIdx.y+i][threadIdx.x] = in[boff + (size_t)(y0+i)*NSZ + x];
    __syncthreads();
    int x2 = blockIdx.y*32 + threadIdx.x, y2 = blockIdx.x*32 + threadIdx.y;
#pragma unroll
    for (int i = 0; i < 32; i += 8)
        out[boff + (size_t)(y2+i)*NSZ + x2] = tile[threadIdx.x][threadIdx.y+i];
}

__global__ void ia_peakA(const float* __restrict__ surf){
    __shared__ float sv[256]; __shared__ int si[256];
    const int b = blockIdx.y, ch = blockIdx.x, t = threadIdx.x;
    const float* p = surf + (size_t)b*NN + ch*32768;
    float bv = -1e30f; int bi = 0;
    for (int i = t; i < 32768; i += 256){
        float vv = p[i];
        if (vv > bv){ bv = vv; bi = i; }
    }
    sv[t] = bv; si[t] = bi; __syncthreads();
    for (int s2 = 128; s2 > 0; s2 >>= 1){
        if (t < s2){
            float v2 = sv[t+s2]; int i2 = si[t+s2];
            if (v2 > sv[t] || (v2 == sv[t] && i2 < si[t])){ sv[t]=v2; si[t]=i2; }
        }
        __syncthreads();
    }
    if (t == 0) g_part[b*8+ch] = make_float2(sv[0], (float)(ch*32768 + si[0]));
}

__global__ void ia_peakB(const float* __restrict__ surf, int mode){
    if (threadIdx.x) return;
    const int b = blockIdx.x;
    float bv = -1e30f; int bi = 1<<30;
    for (int c = 0; c < 8; ++c){
        float2 pv = g_part[b*8+c]; int idx = (int)pv.y;
        if (pv.x > bv || (pv.x == bv && idx < bi)){ bv = pv.x; bi = idx; }
    }
    int r0 = bi >> 9, r1 = bi & 511;
    const float* p = surf + (size_t)b*NN;
    float sub[5][5];
    for (int dy = 0; dy < 5; ++dy)
        for (int dx = 0; dx < 5; ++dx)
            sub[dy][dx] = p[((r0-2+dy)&511)*NSZ + ((r1-2+dx)&511)];
    float s = 0.f;
    for (int dy = 0; dy < 5; ++dy)
        for (int dx = 0; dx < 5; ++dx) s = __fadd_rn(s, sub[dy][dx]);
    float c0 = 0.f, c1 = 0.f;
    for (int d = 0; d < 5; ++d){
        float rs = 0.f, cs = 0.f;
        for (int e = 0; e < 5; ++e){ rs = __fadd_rn(rs, sub[d][e]); cs = __fadd_rn(cs, sub[e][d]); }
        c0 = __fadd_rn(c0, __fmul_rn(rs, (float)d));
        c1 = __fadd_rn(c1, __fmul_rn(cs, (float)d));
    }
    c0 = __fdiv_rn(c0, s); c1 = __fdiv_rn(c1, s);
    float q0 = __fsub_rn(__fadd_rn((float)r0, c0), 2.f);
    float q1 = __fsub_rn(__fadd_rn((float)r1, c1), 2.f);
    q0 = fmodf(__fadd_rn(q0, 0.5f), 512.f); if (q0 < 0.f) q0 = __fadd_rn(q0, 512.f); q0 = __fsub_rn(q0, 0.5f);
    q1 = fmodf(__fadd_rn(q1, 0.5f), 512.f); if (q1 < 0.f) q1 = __fadd_rn(q1, 512.f); q1 = __fsub_rn(q1, 0.5f);
    float a0 = __fsub_rn(q0, 256.f), a1 = __fsub_rn(q1, 256.f);
    if (mode == 0){
        float t = __fmul_rn(-PIF32, a0) * (1.f/512.f);           // /512 exact
        float ang = __fmul_rn(t, 57.29577951308232f);            // degrees (f32 const)
        float w = fmodf(__fadd_rn(ang, 180.f), 360.f); if (w < 0.f) w = __fadd_rn(w, 360.f);
        w = __fsub_rn(w, 180.f);
        float angle = -w;
        g_sc[322+b] = angle;
        float pw = (float)exp((double)a1 * log((double)g_lb));   // correctly-rounded powf
        g_sc[258+b] = __fdiv_rn(1.f, pw);
        float aa = __fmul_rn(angle, 0.017453292519943295f);      // deg2rad f32
        g_sc[578+b] = (float)cos((double)aa);                    // cosA (no overlap now)
        g_sc[514+b] = (float)sin((double)aa);                    // sinA
    } else {
        g_sc[386+2*b]   = a0;
        g_sc[386+2*b+1] = a1;
    }
}

__global__ void __launch_bounds__(256) ia_final(const float* __restrict__ img, float* __restrict__ out){
    int idx = blockIdx.x*blockDim.x + threadIdx.x;
    if (idx >= NB*NN) return;
    int b = idx >> 18, y = (idx >> 9) & 511, x = idx & 511;
    float scl = g_sc[258+b];
    float ty = g_sc[386+2*b], tx = g_sc[386+2*b+1];
    float ca = g_sc[578+b], sa = g_sc[514+b];
    float dy = __fsub_rn(__fsub_rn((float)y, ty), 255.5f);
    float dx = __fsub_rn(__fsub_rn((float)x, tx), 255.5f);
    float sy = __fadd_rn(__fdiv_rn(__fsub_rn(__fmul_rn(ca,dy), __fmul_rn(sa,dx)), scl), 255.5f);
    float sx = __fadd_rn(__fdiv_rn(__fadd_rn(__fmul_rn(sa,dy), __fmul_rn(ca,dx)), scl), 255.5f);
    out[idx] = bilin(img + (size_t)b*NN, sy, sx, g_sc[b]);
}

extern "C" void kernel_launch(void* const* d_in, const int* in_sizes, int n_in,
                              void* d_out, int out_size){
    const float* imgs = (const float*)d_in[0];
    const float* ref  = (const float*)d_in[1];
    if (n_in >= 2 && in_sizes[0] == NN && in_sizes[1] == NB*NN){
        imgs = (const float*)d_in[1];
        ref  = (const float*)d_in[0];
    }
    static float2 *cA=nullptr, *cB, *sA, *sB, *Flp0, *Fref;
    static float *rb, *d0, *sc;
    if (!cA){
        cudaGetSymbolAddress((void**)&cA, g_cA);   cudaGetSymbolAddress((void**)&cB, g_cB);
        cudaGetSymbolAddress((void**)&sA, g_sA);   cudaGetSymbolAddress((void**)&sB, g_sB);
        cudaGetSymbolAddress((void**)&Flp0, g_Flp0); cudaGetSymbolAddress((void**)&Fref, g_Fref);
        cudaGetSymbolAddress((void**)&rb, g_r);    cudaGetSymbolAddress((void**)&d0, g_d0);
        cudaGetSymbolAddress((void**)&sc, g_sc);
    }
    const int BG = NB*512/4, SG = 512/4, GB_ = NB*NN/256;
    const dim3 TB(32,8), TGB(16,16,NB), TG1(16,16,1);
    FftArgs A{};

    ia_setup<<<1,256>>>();
    ia_border_median<<<NB,256>>>(imgs, 5,  sc+0);
    ia_border_median<<<NB,256>>>(imgs, 30, sc+64);
    ia_border_median<<<1, 256>>>(ref,  30, sc+128);

    // Fref = fft2(ref)^T
    A = FftArgs{}; A.srcF = ref; A.dstC = sA;
    ia_fft<1,0,0><<<SG,256>>>(A);
    ia_transpose<<<TG1,TB>>>(sA, sB);
    A = FftArgs{}; A.srcC = sB; A.dstC = Fref;
    ia_fft<0,0,0><<<SG,256>>>(A);

    // ref: apodize -> fft2 -> specmag(d0^T) -> median -> logpolar -> Flp0
    A = FftArgs{}; A.srcF = ref; A.bg = sc+128; A.dstC = sA;
    ia_fft<2,0,0><<<SG,256>>>(A);
    ia_transpose<<<TG1,TB>>>(sA, sB);
    A = FftArgs{}; A.srcC = sB; A.dstF = d0;
    ia_fft<0,1,0><<<SG,256>>>(A);
    ia_border_median<<<1,256>>>(d0, 5, sc+129);
    A = FftArgs{}; A.srcF = d0; A.bg = sc+129; A.dstC = sA;
    ia_fft<3,0,0><<<SG,256>>>(A);
    ia_transpose<<<TG1,TB>>>(sA, sB);
    A = FftArgs{}; A.srcC = sB; A.dstC = Flp0;
    ia_fft<0,0,0><<<SG,256>>>(A);

    // batch: apodize -> fft2 -> specmag(d^T) -> median -> logpolar
    A = FftArgs{}; A.srcF = imgs; A.bg = sc+64; A.dstC = cA;
    ia_fft<2,0,0><<<BG,256>>>(A);
    ia_transpose<<<TGB,TB>>>(cA, cB);
    A = FftArgs{}; A.srcC = cB; A.dstF = rb;
    ia_fft<0,1,0><<<BG,256>>>(A);
    ia_border_median<<<NB,256>>>(rb, 5, sc+130);
    A = FftArgs{}; A.srcF = rb; A.bg = sc+130; A.dstC = cA;
    ia_fft<3,0,0><<<BG,256>>>(A);
    ia_transpose<<<TGB,TB>>>(cA, cB);
    ia_clear<<<1,64>>>();
    A = FftArgs{}; A.srcC = cB; A.dstC = cA;
    ia_fft<0,3,0><<<BG,256>>>(A);                 // cA = F1^T, g_mxu = max|f1|
    A = FftArgs{}; A.srcC = cA; A.F0 = Flp0; A.dstC = cB;
    ia_fft<4,0,1><<<BG,256>>>(A);
    ia_transpose<<<TGB,TB>>>(cB, cA);
    A = FftArgs{}; A.srcC = cA; A.dstF = rb;
    ia_fft<0,2,1><<<BG,256>>>(A);                 // rb = scps
    ia_peakA<<<dim3(8,NB),256>>>(rb);
    ia_peakB<<<NB,32>>>(rb, 0);                   // -> scale, angle, sin/cos

    // corr #2: im_rs (resampled on the fly) vs raw ref
    A = FftArgs{}; A.img = imgs; A.dstC = cA;
    ia_fft<5,0,0><<<BG,256>>>(A);
    ia_transpose<<<TGB,TB>>>(cA, cB);
    ia_clear<<<1,64>>>();
    A = FftArgs{}; A.srcC = cB; A.dstC = cA;
    ia_fft<0,3,0><<<BG,256>>>(A);
    A = FftArgs{}; A.srcC = cA; A.F0 = Fref; A.dstC = cB;
    ia_fft<4,0,1><<<BG,256>>>(A);
    ia_transpose<<<TGB,TB>>>(cB, cA);
    A = FftArgs{}; A.srcC = cA; A.dstF = rb;
    ia_fft<0,2,1><<<BG,256>>>(A);
    ia_peakA<<<dim3(8,NB),256>>>(rb);
    ia_peakB<<<NB,32>>>(rb, 1);                   // -> tvec

    ia_final<<<GB_,256>>>(imgs, (float*)d_out);
}

// round 14
// speedup vs baseline: 1.1844x; 1.1844x over previous
#include <cuda_runtime.h>
#include <math.h>

#define NB   64
#define NSZ  512
#define NN   (NSZ*NSZ)
#define PI_D 3.14159265358979323846
#define PIF32 3.14159274101257324219f
#define PIH32 1.57079637050628662109f

__device__ float2 g_cA[NB*NN];
__device__ float2 g_cB[NB*NN];
__device__ float  g_r [NB*NN];
__device__ float2 g_sA[NN];
__device__ float2 g_sB[NN];
__device__ float2 g_Flp0[NN];
__device__ float2 g_Fref[NN];
__device__ float  g_d0[NN];
// 0 bg_img[64] | 64 bg_apo[64] | 128 bg_apo_ref | 129 bg_lp0 | 130 bg_lp[64] |
// 258 scale[64] | 322 angle[64] | 386 tvec[128](..513) | 514 sinA[64](..577) | 578 cosA[64](..641)
__device__ float    g_sc[700];
__device__ unsigned g_mxu[64];
__device__ float2   g_part[64*8];
__device__ float2 g_tw[512];
__device__ float  g_rad[512], g_ths[512], g_thc[512], g_lin[512];
__device__ double g_apd[512];
__device__ float  g_lb;

__device__ __forceinline__ unsigned fkey(float x){
    unsigned u = __float_as_uint(x);
    return (u & 0x80000000u) ? ~u : (u | 0x80000000u);
}
__device__ __forceinline__ float finv(unsigned k){
    unsigned u = (k & 0x80000000u) ? (k & 0x7FFFFFFFu) : ~k;
    return __uint_as_float(u);
}
// correctly-rounded f32 complex magnitude (glibc hypotf equivalent)
__device__ __forceinline__ float mag32(float x, float y){
    return (float)sqrt((double)x*(double)x + (double)y*(double)y);
}
__device__ __forceinline__ int border_idx(int i, int r){
    if (i < r*NSZ) return i;
    i -= r*NSZ;
    if (i < r*NSZ){ int y = NSZ - r + i/NSZ; return y*NSZ + (i%NSZ); }
    i -= r*NSZ;
    int row = i/(2*r), c = i%(2*r);
    return (r+row)*NSZ + ((c < r) ? c : (NSZ - 2*r + c));
}
// reference fp32 bilinear, exact op order, no contraction
__device__ __forceinline__ float bilin(const float* __restrict__ img, float ry, float rx, float bg){
    float y0f = floorf(ry), x0f = floorf(rx);
    float wy = __fsub_rn(ry, y0f), wx = __fsub_rn(rx, x0f);
    int y0 = (int)y0f, x0 = (int)x0f;
    float v[4];
#pragma unroll
    for (int k = 0; k < 4; ++k){
        int yi = y0 + (k>>1), xi = x0 + (k&1);
        bool ok = (yi>=0)&&(yi<NSZ)&&(xi>=0)&&(xi<NSZ);
        int yc = min(max(yi,0),NSZ-1), xc = min(max(xi,0),NSZ-1);
        v[k] = ok ? img[yc*NSZ+xc] : bg;
    }
    float oy = __fsub_rn(1.f, wy), ox = __fsub_rn(1.f, wx);
    float t0 = __fmul_rn(__fmul_rn(v[0], oy), ox);
    float t1 = __fmul_rn(__fmul_rn(v[1], oy), wx);
    float t2 = __fmul_rn(__fmul_rn(v[2], wy), ox);
    float t3 = __fmul_rn(__fmul_rn(v[3], wy), wx);
    return __fadd_rn(__fadd_rn(__fadd_rn(t0, t1), t2), t3);
}
__device__ __forceinline__ float2 cadd(float2 a, float2 b){ return make_float2(a.x+b.x, a.y+b.y); }
__device__ __forceinline__ float2 csub(float2 a, float2 b){ return make_float2(a.x-b.x, a.y-b.y); }
__device__ __forceinline__ float2 cmul(float2 a, float2 b){
    return make_float2(fmaf(a.x,b.x,-a.y*b.y), fmaf(a.x,b.y, a.y*b.x));
}
__device__ __forceinline__ float2 cmuli(float2 a, float s){ return make_float2(-s*a.y, s*a.x); }
__device__ __forceinline__ void fft8(float2* v, float s){
    float2 b0=cadd(v[0],v[4]), b1=csub(v[0],v[4]);
    float2 b2=cadd(v[2],v[6]), b3=csub(v[2],v[6]);
    float2 b4=cadd(v[1],v[5]), b5=csub(v[1],v[5]);
    float2 b6=cadd(v[3],v[7]), b7=csub(v[3],v[7]);
    float2 t3=cmuli(b3,s), t7=cmuli(b7,s);
    float2 c0=cadd(b0,b2), c2=csub(b0,b2), c1=cadd(b1,t3), c3=csub(b1,t3);
    float2 c4=cadd(b4,b6), c6=csub(b4,b6), c5=cadd(b5,t7), c7=csub(b5,t7);
    const float r2 = 0.70710678118654752440f;
    float2 w1 = make_float2( r2, s*r2), w3 = make_float2(-r2, s*r2);
    float2 d5=cmul(c5,w1), d6=cmuli(c6,s), d7=cmul(c7,w3);
    v[0]=cadd(c0,c4); v[4]=csub(c0,c4);
    v[1]=cadd(c1,d5); v[5]=csub(c1,d5);
    v[2]=cadd(c2,d6); v[6]=csub(c2,d6);
    v[3]=cadd(c3,d7); v[7]=csub(c3,d7);
}
#define SPAD(i) ((i) + ((i)>>3))

struct FftArgs {
    const float2* srcC; const float* srcF;
    float2* dstC; float* dstF;
    const float* bg; const float2* F0; const float* img;
};

// PRE: 0 loadC,1 packF,2 apodize,3 lp-gather,4 crosspow,5 transform
// POST: 0 storeC,1 specmag,2 absshift,3 storeC+max        DIR: 0 fwd, 1 inv
template<int PRE, int POST, int DIR>
__global__ void __launch_bounds__(256) ia_fft(FftArgs A){
    __shared__ float2 sm[4][576];
    __shared__ float2 tws[512];
    __shared__ float  red[256];
    const int tid = threadIdx.x;
    tws[tid] = g_tw[tid]; tws[tid+256] = g_tw[tid+256];
    const int rl = tid >> 6, j = tid & 63;
    const int gr = blockIdx.x*4 + rl;
    const int b = gr >> 9, rr = gr & 511;
    const float sgn = DIR ? 1.f : -1.f;
    float2 v[8];

    if (PRE == 0){
        const float2* s = A.srcC + (size_t)gr*NSZ;
#pragma unroll
        for (int r = 0; r < 8; ++r) v[r] = s[j + 64*r];
    } else if (PRE == 1){
        const float* s = A.srcF + (size_t)gr*NSZ;
#pragma unroll
        for (int r = 0; r < 8; ++r) v[r] = make_float2(s[j+64*r], 0.f);
    } else if (PRE == 2){
        const double ay = g_apd[rr];
        const float bgv = A.bg[b];
        const float* s = A.srcF + (size_t)gr*NSZ;
#pragma unroll
        for (int r = 0; r < 8; ++r){
            int p = j + 64*r;
            float a = (float)(ay * g_apd[p]);   // numpy fp64 outer, rounded once
            float t = __fmul_rn(s[p], a);
            float u = __fmul_rn(bgv, __fsub_rn(1.f, a));
            v[r] = make_float2(__fadd_rn(t, u), 0.f);
        }
    } else if (PRE == 3){
        const float sn = g_ths[rr], cs = g_thc[rr], bgv = A.bg[b];
        const float* dd = A.srcF + (size_t)b*NN;
#pragma unroll
        for (int r = 0; r < 8; ++r){
            int p = j + 64*r;
            float rad = g_rad[p];
            float y = __fadd_rn(__fmul_rn(rad, sn), 256.f);
            float x = __fadd_rn(__fmul_rn(rad, cs), 256.f);
            v[r] = make_float2(bilin(dd, x, y, bgv), 0.f);  // src transposed -> swap
        }
    } else if (PRE == 4){
        const float2* s  = A.srcC + (size_t)gr*NSZ;
        const float2* f0 = A.F0   + (size_t)rr*NSZ;
        const float eps  = __fmul_rn(__uint_as_float(g_mxu[b]), 1e-15f);
#pragma unroll
        for (int r = 0; r < 8; ++r){
            int p = j + 64*r;
            float2 c = s[p], a = f0[p];
            float den = __fadd_rn(__fmul_rn(mag32(a.x,a.y), mag32(c.x,c.y)), eps);
            float re = __fadd_rn(__fmul_rn(a.x,c.x), __fmul_rn(a.y,c.y));
            float im = __fsub_rn(__fmul_rn(a.y,c.x), __fmul_rn(a.x,c.y));
            v[r] = make_float2(__fdiv_rn(re,den), __fdiv_rn(im,den));
        }
    } else {
        float scl = g_sc[258+b];
        float ca = g_sc[578+b], sa = g_sc[514+b];
        const float bgv = g_sc[b];
        const float* im = A.img + (size_t)b*NN;
        float dy = __fsub_rn((float)rr, 255.5f);   // tvec = 0 here
#pragma unroll
        for (int r = 0; r < 8; ++r){
            float dx = __fsub_rn((float)(j + 64*r), 255.5f);
            float sy = __fadd_rn(__fdiv_rn(__fsub_rn(__fmul_rn(ca,dy), __fmul_rn(sa,dx)), scl), 255.5f);
            float sx = __fadd_rn(__fdiv_rn(__fadd_rn(__fmul_rn(sa,dy), __fmul_rn(ca,dx)), scl), 255.5f);
            v[r] = make_float2(bilin(im, sy, sx, bgv), 0.f);
        }
    }

    fft8(v, sgn);
#pragma unroll
    for (int r = 0; r < 8; ++r) sm[rl][SPAD(8*j + r)] = v[r];
    __syncthreads();
#pragma unroll
    for (int r = 0; r < 8; ++r) v[r] = sm[rl][SPAD(j + 64*r)];
    __syncthreads();
    {
        const int kb = (j & 7) * 8;
#pragma unroll
        for (int r = 1; r < 8; ++r){
            float2 w = tws[(kb*r) & 511];
            if (DIR) w.y = -w.y;
            v[r] = cmul(v[r], w);
        }
        fft8(v, sgn);
        const int base = (j >> 3)*64 + (j & 7);
#pragma unroll
        for (int r = 0; r < 8; ++r) sm[rl][SPAD(base + 8*r)] = v[r];
    }
    __syncthreads();
#pragma unroll
    for (int r = 0; r < 8; ++r) v[r] = sm[rl][SPAD(j + 64*r)];
#pragma unroll
    for (int r = 1; r < 8; ++r){
        float2 w = tws[(j*r) & 511];
        if (DIR) w.y = -w.y;
        v[r] = cmul(v[r], w);
    }
    fft8(v, sgn);

    if (POST == 0){
        float2* d = A.dstC + (size_t)gr*NSZ;
        const float s5 = DIR ? (1.f/512.f) : 1.f;   // exact pow2
#pragma unroll
        for (int r = 0; r < 8; ++r) d[j+64*r] = make_float2(v[r].x*s5, v[r].y*s5);
    } else if (POST == 1){
        const int y = (rr + 256) & 511;
        float* d = A.dstF + (size_t)b*NN + (size_t)y*NSZ;
        const float yyv = g_lin[y];
#pragma unroll
        for (int r = 0; r < 8; ++r){
            int x = (j + 64*r + 256) & 511;
            float xxv = g_lin[x];
            float rad = __fsqrt_rn(__fadd_rn(__fmul_rn(yyv,yyv), __fmul_rn(xxv,xxv)));
            float c = (float)cos((double)rad);      // correctly-rounded cosf
            float f = (rad > PIH32) ? 1.0f : __fsub_rn(1.0f, __fmul_rn(c,c));
            d[x] = __fmul_rn(mag32(v[r].x, v[r].y), f);
        }
    } else if (POST == 2){
        const int y = (rr + 256) & 511;
        float* d = A.dstF + (size_t)b*NN + (size_t)y*NSZ;
#pragma unroll
        for (int r = 0; r < 8; ++r){
            int x = (j + 64*r + 256) & 511;
            float xr = __fmul_rn(v[r].x, 1.f/512.f);
            float xi = __fmul_rn(v[r].y, 1.f/512.f);
            d[x] = mag32(xr, xi);
        }
    } else {
        float2* d = A.dstC + (size_t)gr*NSZ;
        float m = 0.f;
#pragma unroll
        for (int r = 0; r < 8; ++r){
            d[j+64*r] = v[r];
            m = fmaxf(m, mag32(v[r].x, v[r].y));
        }
        red[tid] = m; __syncthreads();
        for (int s2 = 128; s2 > 0; s2 >>= 1){
            if (tid < s2) red[tid] = fmaxf(red[tid], red[tid+s2]);
            __syncthreads();
        }
        if (tid == 0) atomicMax(&g_mxu[b], __float_as_uint(red[0]));
    }
}

// 256 threads + stride loop: launch-safe at ANY register count
__global__ void __launch_bounds__(256) ia_setup(){
    // glibc chain: lgf = fl32(log(281.6f)); arg = lgf/512 (exact); lb = fl32(exp(arg))
    const float lgf = (float)log(281.600006103515625);
    const float arg = lgf / 512.0f;
    const float lb  = (float)exp((double)arg);
    const double loglb = log((double)lb);
    for (int i = threadIdx.x; i < 512; i += 256){
        double a = -2.0*PI_D*(double)i/512.0;
        g_tw[i] = make_float2((float)cos(a), (float)sin(a));
        g_rad[i] = (float)exp((double)i * loglb);      // == glibc powf(lb, i)
        float af = __fmul_rn((float)i, PIF32/512.0f);  // exact step pi/512
        g_ths[i] = (float)sin(-(double)af);
        g_thc[i] = (float)cos(-(double)af);
        const float dl = PIF32/511.0f;
        g_lin[i] = __fadd_rn(__fmul_rn((float)i, dl), -PIH32);
        double t0 = 1.0;
        if (i < 61)        t0 = 0.5*(1.0 - cos(2.0*PI_D*(double)i/121.0));
        else if (i >= 451){ int jj = i - 390; t0 = 0.5*(1.0 - cos(2.0*PI_D*(double)jj/121.0)); }
        g_apd[i] = t0;
    }
    if (threadIdx.x == 0) g_lb = lb;
    if (threadIdx.x < 64) g_mxu[threadIdx.x] = 0u;
}
__global__ void ia_clear(){ g_mxu[threadIdx.x] = 0u; }

// Warp-aggregated radix-select border median: one shared atomic per distinct
// bin per warp per iteration (kills same-bin serialization), 512 threads.
// Result is bit-identical to the old kernel (exact order statistics).
__global__ void __launch_bounds__(512) ia_border_median(const float* __restrict__ base, int radius, float* __restrict__ out){
    __shared__ unsigned hist[256];
    __shared__ unsigned s_prefix, s_rank;
    __shared__ float    s_val[2];
    const float* img = base + (size_t)blockIdx.x * NN;
    const int r = radius;
    const int n = 2*r*NSZ + 2*r*(NSZ-2*r);
    const int t = threadIdx.x;
    const int T = 512;
    const int iters = (n + T - 1) / T;
    const int lane = t & 31;
    for (int which = 0; which < 2; ++which){
        int k = n/2 - 1 + which;
        if (t==0){ s_prefix = 0u; s_rank = (unsigned)k; }
        __syncthreads();
        for (int shift = 24; shift >= 0; shift -= 8){
            if (t < 256) hist[t] = 0u;
            __syncthreads();
            unsigned pmask = (shift==24) ? 0u : (0xFFFFFFFFu << (shift+8));
            unsigned pref = s_prefix, rank = s_rank;
            for (int it = 0; it < iters; ++it){
                int i = it*T + t;
                bool ok = false;
                unsigned bin = 0xFFFFFFFFu;
                if (i < n){
                    unsigned key = fkey(img[border_idx(i, r)]);
                    if ((key & pmask) == pref){ ok = true; bin = (key >> shift) & 255u; }
                }
                unsigned grp = __match_any_sync(0xFFFFFFFFu, bin);
                int leader = __ffs(grp) - 1;
                if (ok && lane == leader) atomicAdd(&hist[bin], (unsigned)__popc(grp));
            }
            __syncthreads();
            if (t==0){
                unsigned cum = 0;
                for (int jj = 0; jj < 256; ++jj){
                    unsigned h = hist[jj];
                    if (cum + h > rank){ s_prefix = pref | ((unsigned)jj << shift);
                                         s_rank = rank - cum; break; }
                    cum += h;
                }
            }
            __syncthreads();
        }
        if (t==0) s_val[which] = finv(s_prefix);
        __syncthreads();
    }
    if (t==0) out[blockIdx.x] = __fmul_rn(0.5f, __fadd_rn(s_val[0], s_val[1]));
}

__global__ void ia_transpose(const float2* __restrict__ in, float2* __restrict__ out){
    __shared__ float2 tile[32][33];
    const size_t boff = (size_t)blockIdx.z * NN;
    int x = blockIdx.x*32 + threadIdx.x, y0 = blockIdx.y*32 + threadIdx.y;
#pragma unroll
    for (int i = 0; i < 32; i += 8)
        tile[threadIdx.y+i][threadIdx.x] = in[boff + (size_t)(y0+i)*NSZ + x];
    __syncthreads();
    int x2 = blockIdx.y*32 + threadIdx.x, y2 = blockIdx.x*32 + threadIdx.y;
#pragma unroll
    for (int i = 0; i < 32; i += 8)
        out[boff + (size_t)(y2+i)*NSZ + x2] = tile[threadIdx.x][threadIdx.y+i];
}

__global__ void ia_peakA(const float* __restrict__ surf){
    __shared__ float sv[256]; __shared__ int si[256];
    const int b = blockIdx.y, ch = blockIdx.x, t = threadIdx.x;
    const float* p = surf + (size_t)b*NN + ch*32768;
    float bv = -1e30f; int bi = 0;
    for (int i = t; i < 32768; i += 256){
        float vv = p[i];
        if (vv > bv){ bv = vv; bi = i; }
    }
    sv[t] = bv; si[t] = bi; __syncthreads();
    for (int s2 = 128; s2 > 0; s2 >>= 1){
        if (t < s2){
            float v2 = sv[t+s2]; int i2 = si[t+s2];
            if (v2 > sv[t] || (v2 == sv[t] && i2 < si[t])){ sv[t]=v2; si[t]=i2; }
        }
        __syncthreads();
    }
    if (t == 0) g_part[b*8+ch] = make_float2(sv[0], (float)(ch*32768 + si[0]));
}

__global__ void ia_peakB(const float* __restrict__ surf, int mode){
    if (threadIdx.x) return;
    const int b = blockIdx.x;
    float bv = -1e30f; int bi = 1<<30;
    for (int c = 0; c < 8; ++c){
        float2 pv = g_part[b*8+c]; int idx = (int)pv.y;
        if (pv.x > bv || (pv.x == bv && idx < bi)){ bv = pv.x; bi = idx; }
    }
    int r0 = bi >> 9, r1 = bi & 511;
    const float* p = surf + (size_t)b*NN;
    float sub[5][5];
    for (int dy = 0; dy < 5; ++dy)
        for (int dx = 0; dx < 5; ++dx)
            sub[dy][dx] = p[((r0-2+dy)&511)*NSZ + ((r1-2+dx)&511)];
    float s = 0.f;
    for (int dy = 0; dy < 5; ++dy)
        for (int dx = 0; dx < 5; ++dx) s = __fadd_rn(s, sub[dy][dx]);
    float c0 = 0.f, c1 = 0.f;
    for (int d = 0; d < 5; ++d){
        float rs = 0.f, cs = 0.f;
        for (int e = 0; e < 5; ++e){ rs = __fadd_rn(rs, sub[d][e]); cs = __fadd_rn(cs, sub[e][d]); }
        c0 = __fadd_rn(c0, __fmul_rn(rs, (float)d));
        c1 = __fadd_rn(c1, __fmul_rn(cs, (float)d));
    }
    c0 = __fdiv_rn(c0, s); c1 = __fdiv_rn(c1, s);
    float q0 = __fsub_rn(__fadd_rn((float)r0, c0), 2.f);
    float q1 = __fsub_rn(__fadd_rn((float)r1, c1), 2.f);
    q0 = fmodf(__fadd_rn(q0, 0.5f), 512.f); if (q0 < 0.f) q0 = __fadd_rn(q0, 512.f); q0 = __fsub_rn(q0, 0.5f);
    q1 = fmodf(__fadd_rn(q1, 0.5f), 512.f); if (q1 < 0.f) q1 = __fadd_rn(q1, 512.f); q1 = __fsub_rn(q1, 0.5f);
    float a0 = __fsub_rn(q0, 256.f), a1 = __fsub_rn(q1, 256.f);
    if (mode == 0){
        float t = __fmul_rn(-PIF32, a0) * (1.f/512.f);           // /512 exact
        float ang = __fmul_rn(t, 57.29577951308232f);            // degrees (f32 const)
        float w = fmodf(__fadd_rn(ang, 180.f), 360.f); if (w < 0.f) w = __fadd_rn(w, 360.f);
        w = __fsub_rn(w, 180.f);
        float angle = -w;
        g_sc[322+b] = angle;
        float pw = (float)exp((double)a1 * log((double)g_lb));   // correctly-rounded powf
        g_sc[258+b] = __fdiv_rn(1.f, pw);
        float aa = __fmul_rn(angle, 0.017453292519943295f);      // deg2rad f32
        g_sc[578+b] = (float)cos((double)aa);                    // cosA
        g_sc[514+b] = (float)sin((double)aa);                    // sinA
    } else {
        g_sc[386+2*b]   = a0;
        g_sc[386+2*b+1] = a1;
    }
}

__global__ void __launch_bounds__(256) ia_final(const float* __restrict__ img, float* __restrict__ out){
    int idx = blockIdx.x*blockDim.x + threadIdx.x;
    if (idx >= NB*NN) return;
    int b = idx >> 18, y = (idx >> 9) & 511, x = idx & 511;
    float scl = g_sc[258+b];
    float ty = g_sc[386+2*b], tx = g_sc[386+2*b+1];
    float ca = g_sc[578+b], sa = g_sc[514+b];
    float dy = __fsub_rn(__fsub_rn((float)y, ty), 255.5f);
    float dx = __fsub_rn(__fsub_rn((float)x, tx), 255.5f);
    float sy = __fadd_rn(__fdiv_rn(__fsub_rn(__fmul_rn(ca,dy), __fmul_rn(sa,dx)), scl), 255.5f);
    float sx = __fadd_rn(__fdiv_rn(__fadd_rn(__fmul_rn(sa,dy), __fmul_rn(ca,dx)), scl), 255.5f);
    out[idx] = bilin(img + (size_t)b*NN, sy, sx, g_sc[b]);
}

extern "C" void kernel_launch(void* const* d_in, const int* in_sizes, int n_in,
                              void* d_out, int out_size){
    const float* imgs = (const float*)d_in[0];
    const float* ref  = (const float*)d_in[1];
    if (n_in >= 2 && in_sizes[0] == NN && in_sizes[1] == NB*NN){
        imgs = (const float*)d_in[1];
        ref  = (const float*)d_in[0];
    }
    static float2 *cA=nullptr, *cB, *sA, *sB, *Flp0, *Fref;
    static float *rb, *d0, *sc;
    if (!cA){
        cudaGetSymbolAddress((void**)&cA, g_cA);   cudaGetSymbolAddress((void**)&cB, g_cB);
        cudaGetSymbolAddress((void**)&sA, g_sA);   cudaGetSymbolAddress((void**)&sB, g_sB);
        cudaGetSymbolAddress((void**)&Flp0, g_Flp0); cudaGetSymbolAddress((void**)&Fref, g_Fref);
        cudaGetSymbolAddress((void**)&rb, g_r);    cudaGetSymbolAddress((void**)&d0, g_d0);
        cudaGetSymbolAddress((void**)&sc, g_sc);
    }
    const int BG = NB*512/4, SG = 512/4, GB_ = NB*NN/256;
    const dim3 TB(32,8), TGB(16,16,NB), TG1(16,16,1);
    FftArgs A{};

    ia_setup<<<1,256>>>();
    ia_border_median<<<NB,512>>>(imgs, 5,  sc+0);
    ia_border_median<<<NB,512>>>(imgs, 30, sc+64);
    ia_border_median<<<1, 512>>>(ref,  30, sc+128);

    // Fref = fft2(ref)^T
    A = FftArgs{}; A.srcF = ref; A.dstC = sA;
    ia_fft<1,0,0><<<SG,256>>>(A);
    ia_transpose<<<TG1,TB>>>(sA, sB);
    A = FftArgs{}; A.srcC = sB; A.dstC = Fref;
    ia_fft<0,0,0><<<SG,256>>>(A);

    // ref: apodize -> fft2 -> specmag(d0^T) -> median -> logpolar -> Flp0
    A = FftArgs{}; A.srcF = ref; A.bg = sc+128; A.dstC = sA;
    ia_fft<2,0,0><<<SG,256>>>(A);
    ia_transpose<<<TG1,TB>>>(sA, sB);
    A = FftArgs{}; A.srcC = sB; A.dstF = d0;
    ia_fft<0,1,0><<<SG,256>>>(A);
    ia_border_median<<<1,512>>>(d0, 5, sc+129);
    A = FftArgs{}; A.srcF = d0; A.bg = sc+129; A.dstC = sA;
    ia_fft<3,0,0><<<SG,256>>>(A);
    ia_transpose<<<TG1,TB>>>(sA, sB);
    A = FftArgs{}; A.srcC = sB; A.dstC = Flp0;
    ia_fft<0,0,0><<<SG,256>>>(A);

    // batch: apodize -> fft2 -> specmag(d^T) -> median -> logpolar
    A = FftArgs{}; A.srcF = imgs; A.bg = sc+64; A.dstC = cA;
    ia_fft<2,0,0><<<BG,256>>>(A);
    ia_transpose<<<TGB,TB>>>(cA, cB);
    A = FftArgs{}; A.srcC = cB; A.dstF = rb;
    ia_fft<0,1,0><<<BG,256>>>(A);
    ia_border_median<<<NB,512>>>(rb, 5, sc+130);
    A = FftArgs{}; A.srcF = rb; A.bg = sc+130; A.dstC = cA;
    ia_fft<3,0,0><<<BG,256>>>(A);
    ia_transpose<<<TGB,TB>>>(cA, cB);
    ia_clear<<<1,64>>>();
    A = FftArgs{}; A.srcC = cB; A.dstC = cA;
    ia_fft<0,3,0><<<BG,256>>>(A);                 // cA = F1^T, g_mxu = max|f1|
    A = FftArgs{}; A.srcC = cA; A.F0 = Flp0; A.dstC = cB;
    ia_fft<4,0,1><<<BG,256>>>(A);
    ia_transpose<<<TGB,TB>>>(cB, cA);
    A = FftArgs{}; A.srcC = cA; A.dstF = rb;
    ia_fft<0,2,1><<<BG,256>>>(A);                 // rb = scps
    ia_peakA<<<dim3(8,NB),256>>>(rb);
    ia_peakB<<<NB,32>>>(rb, 0);                   // -> scale, angle, sin/cos

    // corr #2: im_rs (resampled on the fly) vs raw ref
    A = FftArgs{}; A.img = imgs; A.dstC = cA;
    ia_fft<5,0,0><<<BG,256>>>(A);
    ia_transpose<<<TGB,TB>>>(cA, cB);
    ia_clear<<<1,64>>>();
    A = FftArgs{}; A.srcC = cB; A.dstC = cA;
    ia_fft<0,3,0><<<BG,256>>>(A);
    A = FftArgs{}; A.srcC = cA; A.F0 = Fref; A.dstC = cB;
    ia_fft<4,0,1><<<BG,256>>>(A);
    ia_transpose<<<TGB,TB>>>(cB, cA);
    A = FftArgs{}; A.srcC = cA; A.dstF = rb;
    ia_fft<0,2,1><<<BG,256>>>(A);
    ia_peakA<<<dim3(8,NB),256>>>(rb);
    ia_peakB<<<NB,32>>>(rb, 1);                   // -> tvec

    ia_final<<<GB_,256>>>(imgs, (float*)d_out);
}

// round 17
// speedup vs baseline: 1.6616x; 1.4030x over previous
#include <cuda_runtime.h>
#include <math.h>

#define NB   64
#define NSZ  512
#define NN   (NSZ*NSZ)
#define PI_D 3.14159265358979323846
#define PIF32 3.14159274101257324219f
#define PIH32 1.57079637050628662109f
#define NMAX 57840

__device__ float2 g_cA[NB*NN];
__device__ float2 g_cB[NB*NN];
__device__ float  g_r [NB*NN];
__device__ float2 g_sA[NN];
__device__ float2 g_sB[NN];
__device__ float2 g_Flp0[NN];
__device__ float2 g_Fref[NN];
__device__ float  g_d0[NN];
__device__ unsigned g_keys[129*NMAX];
// 0 bg_img[64] | 64 bg_apo[64] | 128 bg_apo_ref | 129 bg_lp0 | 130 bg_lp[64] |
// 258 scale[64] | 322 angle[64] | 386 tvec[128](..513) | 514 sinA[64](..577) | 578 cosA[64](..641)
__device__ float    g_sc[700];
__device__ unsigned g_mxu[64];
__device__ float2   g_part[64*8];
__device__ float2 g_tw[512];
__device__ float  g_rad[512], g_ths[512], g_thc[512], g_lin[512];
__device__ double g_apd[512];
__device__ float  g_lb;

__device__ __forceinline__ unsigned fkey(float x){
    unsigned u = __float_as_uint(x);
    return (u & 0x80000000u) ? ~u : (u | 0x80000000u);
}
__device__ __forceinline__ float finv(unsigned k){
    unsigned u = (k & 0x80000000u) ? (k & 0x7FFFFFFFu) : ~k;
    return __uint_as_float(u);
}
__device__ __forceinline__ float mag32(float x, float y){
    return (float)sqrt((double)x*(double)x + (double)y*(double)y);
}
__device__ __forceinline__ int border_idx(int i, int r){
    if (i < r*NSZ) return i;
    i -= r*NSZ;
    if (i < r*NSZ){ int y = NSZ - r + i/NSZ; return y*NSZ + (i%NSZ); }
    i -= r*NSZ;
    int row = i/(2*r), c = i%(2*r);
    return (r+row)*NSZ + ((c < r) ? c : (NSZ - 2*r + c));
}
// reference fp32 bilinear, exact op order, no contraction
__device__ __forceinline__ float bilin(const float* __restrict__ img, float ry, float rx, float bg){
    float y0f = floorf(ry), x0f = floorf(rx);
    float wy = __fsub_rn(ry, y0f), wx = __fsub_rn(rx, x0f);
    int y0 = (int)y0f, x0 = (int)x0f;
    float v[4];
#pragma unroll
    for (int k = 0; k < 4; ++k){
        int yi = y0 + (k>>1), xi = x0 + (k&1);
        bool ok = (yi>=0)&&(yi<NSZ)&&(xi>=0)&&(xi<NSZ);
        int yc = min(max(yi,0),NSZ-1), xc = min(max(xi,0),NSZ-1);
        v[k] = ok ? img[yc*NSZ+xc] : bg;
    }
    float oy = __fsub_rn(1.f, wy), ox = __fsub_rn(1.f, wx);
    float t0 = __fmul_rn(__fmul_rn(v[0], oy), ox);
    float t1 = __fmul_rn(__fmul_rn(v[1], oy), wx);
    float t2 = __fmul_rn(__fmul_rn(v[2], wy), ox);
    float t3 = __fmul_rn(__fmul_rn(v[3], wy), wx);
    return __fadd_rn(__fadd_rn(__fadd_rn(t0, t1), t2), t3);
}
__device__ __forceinline__ float2 cadd(float2 a, float2 b){ return make_float2(a.x+b.x, a.y+b.y); }
__device__ __forceinline__ float2 csub(float2 a, float2 b){ return make_float2(a.x-b.x, a.y-b.y); }
__device__ __forceinline__ float2 cmul(float2 a, float2 b){
    return make_float2(fmaf(a.x,b.x,-a.y*b.y), fmaf(a.x,b.y, a.y*b.x));
}
__device__ __forceinline__ float2 cmuli(float2 a, float s){ return make_float2(-s*a.y, s*a.x); }
__device__ __forceinline__ void fft8(float2* v, float s){
    float2 b0=cadd(v[0],v[4]), b1=csub(v[0],v[4]);
    float2 b2=cadd(v[2],v[6]), b3=csub(v[2],v[6]);
    float2 b4=cadd(v[1],v[5]), b5=csub(v[1],v[5]);
    float2 b6=cadd(v[3],v[7]), b7=csub(v[3],v[7]);
    float2 t3=cmuli(b3,s), t7=cmuli(b7,s);
    float2 c0=cadd(b0,b2), c2=csub(b0,b2), c1=cadd(b1,t3), c3=csub(b1,t3);
    float2 c4=cadd(b4,b6), c6=csub(b4,b6), c5=cadd(b5,t7), c7=csub(b5,t7);
    const float r2 = 0.70710678118654752440f;
    float2 w1 = make_float2( r2, s*r2), w3 = make_float2(-r2, s*r2);
    float2 d5=cmul(c5,w1), d6=cmuli(c6,s), d7=cmul(c7,w3);
    v[0]=cadd(c0,c4); v[4]=csub(c0,c4);
    v[1]=cadd(c1,d5); v[5]=csub(c1,d5);
    v[2]=cadd(c2,d6); v[6]=csub(c2,d6);
    v[3]=cadd(c3,d7); v[7]=csub(c3,d7);
}
#define SPAD(i) ((i) + ((i)>>3))

struct FftArgs {
    const float2* srcC; const float* srcF;
    float2* dstC; float* dstF;
    const float* bg; const float2* F0; const float* img;
};

// PRE: 0 loadC,1 packF,2 apodize,3 lp-gather,4 crosspow,5 transform
// POST: 0 storeC,1 specmag,2 absshift,3 storeC+max        DIR: 0 fwd, 1 inv
template<int PRE, int POST, int DIR>
__global__ void __launch_bounds__(256) ia_fft(FftArgs A){
    __shared__ float2 sm[4][576];
    __shared__ float2 tws[512];
    __shared__ float  red[256];
    const int tid = threadIdx.x;
    tws[tid] = g_tw[tid]; tws[tid+256] = g_tw[tid+256];
    const int rl = tid >> 6, j = tid & 63;
    const int gr = blockIdx.x*4 + rl;
    const int b = gr >> 9, rr = gr & 511;
    const float sgn = DIR ? 1.f : -1.f;
    float2 v[8];

    if (PRE == 0){
        const float2* s = A.srcC + (size_t)gr*NSZ;
#pragma unroll
        for (int r = 0; r < 8; ++r) v[r] = s[j + 64*r];
    } else if (PRE == 1){
        const float* s = A.srcF + (size_t)gr*NSZ;
#pragma unroll
        for (int r = 0; r < 8; ++r) v[r] = make_float2(s[j+64*r], 0.f);
    } else if (PRE == 2){
        const double ay = g_apd[rr];
        const float bgv = A.bg[b];
        const float* s = A.srcF + (size_t)gr*NSZ;
#pragma unroll
        for (int r = 0; r < 8; ++r){
            int p = j + 64*r;
            float a = (float)(ay * g_apd[p]);
            float t = __fmul_rn(s[p], a);
            float u = __fmul_rn(bgv, __fsub_rn(1.f, a));
            v[r] = make_float2(__fadd_rn(t, u), 0.f);
        }
    } else if (PRE == 3){
        const float sn = g_ths[rr], cs = g_thc[rr], bgv = A.bg[b];
        const float* dd = A.srcF + (size_t)b*NN;
#pragma unroll
        for (int r = 0; r < 8; ++r){
            int p = j + 64*r;
            float rad = g_rad[p];
            float y = __fadd_rn(__fmul_rn(rad, sn), 256.f);
            float x = __fadd_rn(__fmul_rn(rad, cs), 256.f);
            v[r] = make_float2(bilin(dd, x, y, bgv), 0.f);  // src transposed -> swap
        }
    } else if (PRE == 4){
        const float2* s  = A.srcC + (size_t)gr*NSZ;
        const float2* f0 = A.F0   + (size_t)rr*NSZ;
        const float eps  = __fmul_rn(__uint_as_float(g_mxu[b]), 1e-15f);
#pragma unroll
        for (int r = 0; r < 8; ++r){
            int p = j + 64*r;
            float2 c = s[p], a = f0[p];
            float den = __fadd_rn(__fmul_rn(mag32(a.x,a.y), mag32(c.x,c.y)), eps);
            float re = __fadd_rn(__fmul_rn(a.x,c.x), __fmul_rn(a.y,c.y));
            float im = __fsub_rn(__fmul_rn(a.y,c.x), __fmul_rn(a.x,c.y));
            v[r] = make_float2(__fdiv_rn(re,den), __fdiv_rn(im,den));
        }
    } else {
        float scl = g_sc[258+b];
        float ca = g_sc[578+b], sa = g_sc[514+b];
        const float bgv = g_sc[b];
        const float* im = A.img + (size_t)b*NN;
        float dy = __fsub_rn((float)rr, 255.5f);   // tvec = 0 here
#pragma unroll
        for (int r = 0; r < 8; ++r){
            float dx = __fsub_rn((float)(j + 64*r), 255.5f);
            float sy = __fadd_rn(__fdiv_rn(__fsub_rn(__fmul_rn(ca,dy), __fmul_rn(sa,dx)), scl), 255.5f);
            float sx = __fadd_rn(__fdiv_rn(__fadd_rn(__fmul_rn(sa,dy), __fmul_rn(ca,dx)), scl), 255.5f);
            v[r] = make_float2(bilin(im, sy, sx, bgv), 0.f);
        }
    }

    fft8(v, sgn);
#pragma unroll
    for (int r = 0; r < 8; ++r) sm[rl][SPAD(8*j + r)] = v[r];
    __syncthreads();
#pragma unroll
    for (int r = 0; r < 8; ++r) v[r] = sm[rl][SPAD(j + 64*r)];
    __syncthreads();
    {
        const int kb = (j & 7) * 8;
#pragma unroll
        for (int r = 1; r < 8; ++r){
            float2 w = tws[(kb*r) & 511];
            if (DIR) w.y = -w.y;
            v[r] = cmul(v[r], w);
        }
        fft8(v, sgn);
        const int base = (j >> 3)*64 + (j & 7);
#pragma unroll
        for (int r = 0; r < 8; ++r) sm[rl][SPAD(base + 8*r)] = v[r];
    }
    __syncthreads();
#pragma unroll
    for (int r = 0; r < 8; ++r) v[r] = sm[rl][SPAD(j + 64*r)];
#pragma unroll
    for (int r = 1; r < 8; ++r){
        float2 w = tws[(j*r) & 511];
        if (DIR) w.y = -w.y;
        v[r] = cmul(v[r], w);
    }
    fft8(v, sgn);

    if (POST == 0){
        float2* d = A.dstC + (size_t)gr*NSZ;
        const float s5 = DIR ? (1.f/512.f) : 1.f;
#pragma unroll
        for (int r = 0; r < 8; ++r) d[j+64*r] = make_float2(v[r].x*s5, v[r].y*s5);
    } else if (POST == 1){
        const int y = (rr + 256) & 511;
        float* d = A.dstF + (size_t)b*NN + (size_t)y*NSZ;
        const float yyv = g_lin[y];
#pragma unroll
        for (int r = 0; r < 8; ++r){
            int x = (j + 64*r + 256) & 511;
            float xxv = g_lin[x];
            float rad = __fsqrt_rn(__fadd_rn(__fmul_rn(yyv,yyv), __fmul_rn(xxv,xxv)));
            float c = (float)cos((double)rad);
            float f = (rad > PIH32) ? 1.0f : __fsub_rn(1.0f, __fmul_rn(c,c));
            d[x] = __fmul_rn(mag32(v[r].x, v[r].y), f);
        }
    } else if (POST == 2){
        const int y = (rr + 256) & 511;
        float* d = A.dstF + (size_t)b*NN + (size_t)y*NSZ;
#pragma unroll
        for (int r = 0; r < 8; ++r){
            int x = (j + 64*r + 256) & 511;
            float xr = __fmul_rn(v[r].x, 1.f/512.f);
            float xi = __fmul_rn(v[r].y, 1.f/512.f);
            d[x] = mag32(xr, xi);
        }
    } else {
        float2* d = A.dstC + (size_t)gr*NSZ;
        float m = 0.f;
#pragma unroll
        for (int r = 0; r < 8; ++r){
            d[j+64*r] = v[r];
            m = fmaxf(m, mag32(v[r].x, v[r].y));
        }
        red[tid] = m; __syncthreads();
        for (int s2 = 128; s2 > 0; s2 >>= 1){
            if (tid < s2) red[tid] = fmaxf(red[tid], red[tid+s2]);
            __syncthreads();
        }
        if (tid == 0) atomicMax(&g_mxu[b], __float_as_uint(red[0]));
    }
}

__global__ void __launch_bounds__(256) ia_setup(){
    const float lgf = (float)log(281.600006103515625);
    const float arg = lgf / 512.0f;
    const float lb  = (float)exp((double)arg);
    const double loglb = log((double)lb);
    for (int i = threadIdx.x; i < 512; i += 256){
        double a = -2.0*PI_D*(double)i/512.0;
        g_tw[i] = make_float2((float)cos(a), (float)sin(a));
        g_rad[i] = (float)exp((double)i * loglb);
        float af = __fmul_rn((float)i, PIF32/512.0f);
        g_ths[i] = (float)sin(-(double)af);
        g_thc[i] = (float)cos(-(double)af);
        const float dl = PIF32/511.0f;
        g_lin[i] = __fadd_rn(__fmul_rn((float)i, dl), -PIH32);
        double t0 = 1.0;
        if (i < 61)        t0 = 0.5*(1.0 - cos(2.0*PI_D*(double)i/121.0));
        else if (i >= 451){ int jj = i - 390; t0 = 0.5*(1.0 - cos(2.0*PI_D*(double)jj/121.0)); }
        g_apd[i] = t0;
    }
    if (threadIdx.x == 0) g_lb = lb;
    if (threadIdx.x < 64) g_mxu[threadIdx.x] = 0u;
}
__global__ void ia_clear(){ g_mxu[threadIdx.x] = 0u; }

// Dense-scratch radix-select median. Phase 0: gather+fkey -> dense keys (once).
// Passes: MLP=8 batched reads + warp-aggregated histogram + parallel bin scan.
// Bit-identical result to prior version (exact order statistics).
__device__ __forceinline__ void median_body(const float* __restrict__ img, int r,
                                            float* __restrict__ out,
                                            unsigned* __restrict__ keys){
    __shared__ unsigned hist[256], scn[256];
    __shared__ unsigned s_prefix, s_rank;
    __shared__ float s_val[2];
    const int n = 2*r*NSZ + 2*r*(NSZ-2*r);
    const int t = threadIdx.x, T = 512, lane = t & 31;
    for (int i = t; i < n; i += T) keys[i] = fkey(img[border_idx(i, r)]);
    __syncthreads();
    for (int which = 0; which < 2; ++which){
        int k = n/2 - 1 + which;
        if (t==0){ s_prefix = 0u; s_rank = (unsigned)k; }
        __syncthreads();
        for (int shift = 24; shift >= 0; shift -= 8){
            if (t < 256) hist[t] = 0u;
            __syncthreads();
            unsigned pmask = (shift==24) ? 0u : (0xFFFFFFFFu << (shift+8));
            unsigned pref = s_prefix;
            for (int base = 0; base < n; base += T*8){
                unsigned kk[8]; int ii[8];
#pragma unroll
                for (int v2 = 0; v2 < 8; ++v2){
                    ii[v2] = base + v2*T + t;
                    kk[v2] = (ii[v2] < n) ? keys[ii[v2]] : 0u;
                }
#pragma unroll
                for (int v2 = 0; v2 < 8; ++v2){
                    unsigned bin = 0x100u;
                    if (ii[v2] < n && (kk[v2] & pmask) == pref) bin = (kk[v2] >> shift) & 255u;
                    unsigned grp = __match_any_sync(0xFFFFFFFFu, bin);
                    if (bin != 0x100u && lane == (__ffs(grp)-1))
                        atomicAdd(&hist[bin], (unsigned)__popc(grp));
                }
            }
            __syncthreads();
            if (t < 256) scn[t] = hist[t];
            __syncthreads();
            for (int off = 1; off < 256; off <<= 1){
                unsigned val = 0;
                if (t < 256 && t >= off) val = scn[t-off];
                __syncthreads();
                if (t < 256) scn[t] += val;
                __syncthreads();
            }
            unsigned rank_l = s_rank;
            __syncthreads();
            if (t < 256){
                unsigned hi = scn[t], lo = hi - hist[t];
                if (rank_l >= lo && rank_l < hi){
                    s_prefix = pref | ((unsigned)t << shift);
                    s_rank   = rank_l - lo;
                }
            }
            __syncthreads();
        }
        if (t==0) s_val[which] = finv(s_prefix);
        __syncthreads();
    }
    if (t==0) *out = __fmul_rn(0.5f, __fadd_rn(s_val[0], s_val[1]));
}

// blocks 0..63: imgs r5 -> sc[b]; 64..127: imgs r30 -> sc[64+b]; 128: ref r30 -> sc[128]
__global__ void __launch_bounds__(512) ia_median3(const float* __restrict__ imgs,
                                                  const float* __restrict__ ref,
                                                  float* __restrict__ sc){
    int blk = blockIdx.x;
    unsigned* keys = g_keys + (size_t)blk*NMAX;
    if (blk < 64)       median_body(imgs + (size_t)blk*NN, 5,  sc + blk, keys);
    else if (blk < 128) median_body(imgs + (size_t)(blk-64)*NN, 30, sc + 64 + (blk-64), keys);
    else                median_body(ref, 30, sc + 128, keys);
}

__global__ void __launch_bounds__(512) ia_median_one(const float* __restrict__ src,
                                                     int radius, float* __restrict__ out){
    int blk = blockIdx.x;
    median_body(src + (size_t)blk*NN, radius, out + blk, g_keys + (size_t)blk*NMAX);
}

__global__ void ia_transpose(const float2* __restrict__ in, float2* __restrict__ out){
    __shared__ float2 tile[32][33];
    const size_t boff = (size_t)blockIdx.z * NN;
    int x = blockIdx.x*32 + threadIdx.x, y0 = blockIdx.y*32 + threadIdx.y;
#pragma unroll
    for (int i = 0; i < 32; i += 8)
        tile[threadIdx.y+i][threadIdx.x] = in[boff + (size_t)(y0+i)*NSZ + x];
    __syncthreads();
    int x2 = blockIdx.y*32 + threadIdx.x, y2 = blockIdx.x*32 + threadIdx.y;
#pragma unroll
    for (int i = 0; i < 32; i += 8)
        out[boff + (size_t)(y2+i)*NSZ + x2] = tile[threadIdx.x][threadIdx.y+i];
}

__global__ void ia_peakA(const float* __restrict__ surf){
    __shared__ float sv[256]; __shared__ int si[256];
    const int b = blockIdx.y, ch = blockIdx.x, t = threadIdx.x;
    const float* p = surf + (size_t)b*NN + ch*32768;
    float bv = -1e30f; int bi = 0;
    for (int i = t; i < 32768; i += 256){
        float vv = p[i];
        if (vv > bv){ bv = vv; bi = i; }
    }
    sv[t] = bv; si[t] = bi; __syncthreads();
    for (int s2 = 128; s2 > 0; s2 >>= 1){
        if (t < s2){
            float v2 = sv[t+s2]; int i2 = si[t+s2];
            if (v2 > sv[t] || (v2 == sv[t] && i2 < si[t])){ sv[t]=v2; si[t]=i2; }
        }
        __syncthreads();
    }
    if (t == 0) g_part[b*8+ch] = make_float2(sv[0], (float)(ch*32768 + si[0]));
}

__global__ void ia_peakB(const float* __restrict__ surf, int mode){
    if (threadIdx.x) return;
    const int b = blockIdx.x;
    float bv = -1e30f; int bi = 1<<30;
    for (int c = 0; c < 8; ++c){
        float2 pv = g_part[b*8+c]; int idx = (int)pv.y;
        if (pv.x > bv || (pv.x == bv && idx < bi)){ bv = pv.x; bi = idx; }
    }
    int r0 = bi >> 9, r1 = bi & 511;
    const float* p = surf + (size_t)b*NN;
    float sub[5][5];
    for (int dy = 0; dy < 5; ++dy)
        for (int dx = 0; dx < 5; ++dx)
            sub[dy][dx] = p[((r0-2+dy)&511)*NSZ + ((r1-2+dx)&511)];
    float s = 0.f;
    for (int dy = 0; dy < 5; ++dy)
        for (int dx = 0; dx < 5; ++dx) s = __fadd_rn(s, sub[dy][dx]);
    float c0 = 0.f, c1 = 0.f;
    for (int d = 0; d < 5; ++d){
        float rs = 0.f, cs = 0.f;
        for (int e = 0; e < 5; ++e){ rs = __fadd_rn(rs, sub[d][e]); cs = __fadd_rn(cs, sub[e][d]); }
        c0 = __fadd_rn(c0, __fmul_rn(rs, (float)d));
        c1 = __fadd_rn(c1, __fmul_rn(cs, (float)d));
    }
    c0 = __fdiv_rn(c0, s); c1 = __fdiv_rn(c1, s);
    float q0 = __fsub_rn(__fadd_rn((float)r0, c0), 2.f);
    float q1 = __fsub_rn(__fadd_rn((float)r1, c1), 2.f);
    q0 = fmodf(__fadd_rn(q0, 0.5f), 512.f); if (q0 < 0.f) q0 = __fadd_rn(q0, 512.f); q0 = __fsub_rn(q0, 0.5f);
    q1 = fmodf(__fadd_rn(q1, 0.5f), 512.f); if (q1 < 0.f) q1 = __fadd_rn(q1, 512.f); q1 = __fsub_rn(q1, 0.5f);
    float a0 = __fsub_rn(q0, 256.f), a1 = __fsub_rn(q1, 256.f);
    if (mode == 0){
        float t = __fmul_rn(-PIF32, a0) * (1.f/512.f);
        float ang = __fmul_rn(t, 57.29577951308232f);
        float w = fmodf(__fadd_rn(ang, 180.f), 360.f); if (w < 0.f) w = __fadd_rn(w, 360.f);
        w = __fsub_rn(w, 180.f);
        float angle = -w;
        g_sc[322+b] = angle;
        float pw = (float)exp((double)a1 * log((double)g_lb));
        g_sc[258+b] = __fdiv_rn(1.f, pw);
        float aa = __fmul_rn(angle, 0.017453292519943295f);
        g_sc[578+b] = (float)cos((double)aa);
        g_sc[514+b] = (float)sin((double)aa);
    } else {
        g_sc[386+2*b]   = a0;
        g_sc[386+2*b+1] = a1;
    }
}

__global__ void __launch_bounds__(256) ia_final(const float* __restrict__ img, float* __restrict__ out){
    int idx = blockIdx.x*blockDim.x + threadIdx.x;
    if (idx >= NB*NN) return;
    int b = idx >> 18, y = (idx >> 9) & 511, x = idx & 511;
    float scl = g_sc[258+b];
    float ty = g_sc[386+2*b], tx = g_sc[386+2*b+1];
    float ca = g_sc[578+b], sa = g_sc[514+b];
    float dy = __fsub_rn(__fsub_rn((float)y, ty), 255.5f);
    float dx = __fsub_rn(__fsub_rn((float)x, tx), 255.5f);
    float sy = __fadd_rn(__fdiv_rn(__fsub_rn(__fmul_rn(ca,dy), __fmul_rn(sa,dx)), scl), 255.5f);
    float sx = __fadd_rn(__fdiv_rn(__fadd_rn(__fmul_rn(sa,dy), __fmul_rn(ca,dx)), scl), 255.5f);
    out[idx] = bilin(img + (size_t)b*NN, sy, sx, g_sc[b]);
}

extern "C" void kernel_launch(void* const* d_in, const int* in_sizes, int n_in,
                              void* d_out, int out_size){
    const float* imgs = (const float*)d_in[0];
    const float* ref  = (const float*)d_in[1];
    if (n_in >= 2 && in_sizes[0] == NN && in_sizes[1] == NB*NN){
        imgs = (const float*)d_in[1];
        ref  = (const float*)d_in[0];
    }
    static float2 *cA=nullptr, *cB, *sA, *sB, *Flp0, *Fref;
    static float *rb, *d0, *sc;
    if (!cA){
        cudaGetSymbolAddress((void**)&cA, g_cA);   cudaGetSymbolAddress((void**)&cB, g_cB);
        cudaGetSymbolAddress((void**)&sA, g_sA);   cudaGetSymbolAddress((void**)&sB, g_sB);
        cudaGetSymbolAddress((void**)&Flp0, g_Flp0); cudaGetSymbolAddress((void**)&Fref, g_Fref);
        cudaGetSymbolAddress((void**)&rb, g_r);    cudaGetSymbolAddress((void**)&d0, g_d0);
        cudaGetSymbolAddress((void**)&sc, g_sc);
    }
    const int BG = NB*512/4, SG = 512/4, GB_ = NB*NN/256;
    const dim3 TB(32,8), TGB(16,16,NB), TG1(16,16,1);
    FftArgs A{};

    ia_setup<<<1,256>>>();
    ia_median3<<<129,512>>>(imgs, ref, sc);       // bg_img, bg_apo, bg_apo_ref

    // Fref = fft2(ref)^T
    A = FftArgs{}; A.srcF = ref; A.dstC = sA;
    ia_fft<1,0,0><<<SG,256>>>(A);
    ia_transpose<<<TG1,TB>>>(sA, sB);
    A = FftArgs{}; A.srcC = sB; A.dstC = Fref;
    ia_fft<0,0,0><<<SG,256>>>(A);

    // ref: apodize -> fft2 -> specmag(d0^T) -> median -> logpolar -> Flp0
    A = FftArgs{}; A.srcF = ref; A.bg = sc+128; A.dstC = sA;
    ia_fft<2,0,0><<<SG,256>>>(A);
    ia_transpose<<<TG1,TB>>>(sA, sB);
    A = FftArgs{}; A.srcC = sB; A.dstF = d0;
    ia_fft<0,1,0><<<SG,256>>>(A);
    ia_median_one<<<1,512>>>(d0, 5, sc+129);
    A = FftArgs{}; A.srcF = d0; A.bg = sc+129; A.dstC = sA;
    ia_fft<3,0,0><<<SG,256>>>(A);
    ia_transpose<<<TG1,TB>>>(sA, sB);
    A = FftArgs{}; A.srcC = sB; A.dstC = Flp0;
    ia_fft<0,0,0><<<SG,256>>>(A);

    // batch: apodize -> fft2 -> specmag(d^T) -> median -> logpolar
    A = FftArgs{}; A.srcF = imgs; A.bg = sc+64; A.dstC = cA;
    ia_fft<2,0,0><<<BG,256>>>(A);
    ia_transpose<<<TGB,TB>>>(cA, cB);
    A = FftArgs{}; A.srcC = cB; A.dstF = rb;
    ia_fft<0,1,0><<<BG,256>>>(A);
    ia_median_one<<<64,512>>>(rb, 5, sc+130);
    A = FftArgs{}; A.srcF = rb; A.bg = sc+130; A.dstC = cA;
    ia_fft<3,0,0><<<BG,256>>>(A);
    ia_transpose<<<TGB,TB>>>(cA, cB);
    ia_clear<<<1,64>>>();
    A = FftArgs{}; A.srcC = cB; A.dstC = cA;
    ia_fft<0,3,0><<<BG,256>>>(A);                 // cA = F1^T, g_mxu = max|f1|
    A = FftArgs{}; A.srcC = cA; A.F0 = Flp0; A.dstC = cB;
    ia_fft<4,0,1><<<BG,256>>>(A);
    ia_transpose<<<TGB,TB>>>(cB, cA);
    A = FftArgs{}; A.srcC = cA; A.dstF = rb;
    ia_fft<0,2,1><<<BG,256>>>(A);                 // rb = scps
    ia_peakA<<<dim3(8,NB),256>>>(rb);
    ia_peakB<<<NB,32>>>(rb, 0);                   // -> scale, angle, sin/cos

    // corr #2: im_rs (resampled on the fly) vs raw ref
    A = FftArgs{}; A.img = imgs; A.dstC = cA;
    ia_fft<5,0,0><<<BG,256>>>(A);
    ia_transpose<<<TGB,TB>>>(cA, cB);
    ia_clear<<<1,64>>>();
    A = FftArgs{}; A.srcC = cB; A.dstC = cA;
    ia_fft<0,3,0><<<BG,256>>>(A);
    A = FftArgs{}; A.srcC = cA; A.F0 = Fref; A.dstC = cB;
    ia_fft<4,0,1><<<BG,256>>>(A);
    ia_transpose<<<TGB,TB>>>(cB, cA);
    A = FftArgs{}; A.srcC = cA; A.dstF = rb;
    ia_fft<0,2,1><<<BG,256>>>(A);
    ia_peakA<<<dim3(8,NB),256>>>(rb);
    ia_peakB<<<NB,32>>>(rb, 1);                   // -> tvec

    ia_final<<<GB_,256>>>(imgs, (float*)d_out);
}